// round 1
// baseline (speedup 1.0000x reference)
#include <cuda_runtime.h>
#include <math.h>

// Problem shape (fixed by the reference)
#define BB 64
#define SS 2048
#define DD 256
#define NSPLIT 16
#define CHUNK (SS / NSPLIT)   // 128 rows of S per CTA in pass 1

// Scratch for partial reductions (no dynamic allocation allowed)
__device__ float g_psum[BB * NSPLIT * DD];
__device__ float g_pmax[BB * NSPLIT * DD];
__device__ float g_pcnt[BB * NSPLIT];

__device__ __forceinline__ float neg_inf() { return __int_as_float(0xff800000); }

// Pass 1: each CTA reduces CHUNK rows of S for one (b, split).
// Block = 256 threads: d4 = tid % 64 (float4 lane over D=256), sg = tid / 64 (4 s-rows in parallel).
__global__ __launch_bounds__(256) void pool_pass1(const float* __restrict__ feats,
                                                  const float* __restrict__ mask) {
    const int split = blockIdx.x;
    const int b     = blockIdx.y;
    const int tid   = threadIdx.x;
    const int d4    = tid & 63;
    const int sg    = tid >> 6;

    const float4* __restrict__ frow =
        reinterpret_cast<const float4*>(feats + (size_t)b * SS * DD);
    const float* __restrict__ mrow = mask + (size_t)b * SS;

    float4 sum = make_float4(0.f, 0.f, 0.f, 0.f);
    float4 mx  = make_float4(neg_inf(), neg_inf(), neg_inf(), neg_inf());
    float  cnt = 0.f;

    const int s0 = split * CHUNK;
#pragma unroll 4
    for (int s = s0 + sg; s < s0 + CHUNK; s += 4) {
        float  m = mrow[s];
        float4 f = frow[(size_t)s * 64 + d4];
        bool   v = (m > 0.f);
        cnt += m;
        sum.x += f.x * m;  sum.y += f.y * m;
        sum.z += f.z * m;  sum.w += f.w * m;
        mx.x = fmaxf(mx.x, v ? f.x : neg_inf());
        mx.y = fmaxf(mx.y, v ? f.y : neg_inf());
        mx.z = fmaxf(mx.z, v ? f.z : neg_inf());
        mx.w = fmaxf(mx.w, v ? f.w : neg_inf());
    }

    __shared__ float4 s_sum[256];
    __shared__ float4 s_max[256];
    __shared__ float  s_cnt[4];
    s_sum[tid] = sum;
    s_max[tid] = mx;
    if (d4 == 0) s_cnt[sg] = cnt;
    __syncthreads();

    if (tid < 64) {
        float4 a = s_sum[tid];
        float4 m = s_max[tid];
#pragma unroll
        for (int k = 1; k < 4; ++k) {
            float4 a2 = s_sum[tid + 64 * k];
            float4 m2 = s_max[tid + 64 * k];
            a.x += a2.x; a.y += a2.y; a.z += a2.z; a.w += a2.w;
            m.x = fmaxf(m.x, m2.x); m.y = fmaxf(m.y, m2.y);
            m.z = fmaxf(m.z, m2.z); m.w = fmaxf(m.w, m2.w);
        }
        const size_t base = ((size_t)b * NSPLIT + split) * DD;
        reinterpret_cast<float4*>(g_psum + base)[tid] = a;
        reinterpret_cast<float4*>(g_pmax + base)[tid] = m;
        if (tid == 0)
            g_pcnt[b * NSPLIT + split] = s_cnt[0] + s_cnt[1] + s_cnt[2] + s_cnt[3];
    }
}

// Pass 2: combine NSPLIT partials per (b, d). Output layout: [B, 2*D] = [max | mean].
__global__ __launch_bounds__(256) void pool_pass2(float* __restrict__ out) {
    const int b = blockIdx.x;
    const int d = threadIdx.x;   // 0..255

    float sum = 0.f;
    float mx  = neg_inf();
    float cnt = 0.f;
#pragma unroll
    for (int sp = 0; sp < NSPLIT; ++sp) {
        const size_t base = ((size_t)b * NSPLIT + sp) * DD;
        sum += g_psum[base + d];
        mx   = fmaxf(mx, g_pmax[base + d]);
        cnt += g_pcnt[b * NSPLIT + sp];
    }
    out[(size_t)b * (2 * DD) + d]      = mx;
    out[(size_t)b * (2 * DD) + DD + d] = sum / cnt;
}

extern "C" void kernel_launch(void* const* d_in, const int* in_sizes, int n_in,
                              void* d_out, int out_size) {
    const float* feats = (const float*)d_in[0];
    const float* mask  = (const float*)d_in[1];
    float* out = (float*)d_out;

    dim3 grid1(NSPLIT, BB);
    pool_pass1<<<grid1, 256>>>(feats, mask);
    pool_pass2<<<BB, 256>>>(out);
}